// round 8
// baseline (speedup 1.0000x reference)
#include <cuda_runtime.h>
#include <cooperative_groups.h>

namespace cg = cooperative_groups;

// Problem constants
#define BB 8
#define KK 65536
#define NN 1024
#define CC 128

// FPS kernel config
#define CLUSTER_X 8
#define TPB 1024
#define NWARP (TPB / 32)
#define PTS_PER_CTA (KK / CLUSTER_X)        // 8192
#define PTS_PER_THREAD (PTS_PER_CTA / TPB)  // 8
#define PAIRS (PTS_PER_THREAD / 2)          // 4

// Output layout (float32, concatenated in reference-return order):
//   [0,        BB*NN*3)                 new_xyz      (B, n, 3)
//   [OFF_FEAT, OFF_FEAT + BB*CC*NN)     new_features (B, C, n)
//   [OFF_INDS, OFF_INDS + BB*NN)        sample_inds  (B, n) as float
#define OFF_FEAT (BB * NN * 3)
#define OFF_INDS (OFF_FEAT + BB * CC * NN)

// Scratch for integer indices (device global: allocations are forbidden)
__device__ int g_inds[BB * NN];

// ---- packed f32x2 helpers (Blackwell FADD2/FMUL2; IEEE-exact per lane) ----
#define MUL_F32X2(out, a, b) \
    asm("mul.rn.f32x2 %0, %1, %2;" : "=l"(out) : "l"(a), "l"(b))
#define ADD_F32X2(out, a, b) \
    asm("add.rn.f32x2 %0, %1, %2;" : "=l"(out) : "l"(a), "l"(b))
#define PACK_F32X2(out, lo, hi) \
    asm("mov.b64 %0, {%1, %2};" : "=l"(out) : "f"(lo), "f"(hi))
#define UNPACK_F32X2(lo, hi, in) \
    asm("mov.b64 {%0, %1}, %2;" : "=f"(lo), "=f"(hi) : "l"(in))

// ---- mbarrier / DSMEM helpers ----
__device__ __forceinline__ unsigned smem_addr_u32(const void* p) {
    return (unsigned)__cvta_generic_to_shared(p);
}
__device__ __forceinline__ void mbar_init(unsigned addr, unsigned count) {
    asm volatile("mbarrier.init.shared.b64 [%0], %1;" :: "r"(addr), "r"(count)
                 : "memory");
}
// Map a local shared address into cluster CTA `rank`'s window.
__device__ __forceinline__ unsigned mapa_rank(unsigned local_addr,
                                              unsigned rank) {
    unsigned ra;
    asm volatile("mapa.shared::cluster.u32 %0, %1, %2;"
                 : "=r"(ra) : "r"(local_addr), "r"(rank));
    return ra;
}
__device__ __forceinline__ void dsmem_st_v2u64(unsigned addr,
                                               unsigned long long a,
                                               unsigned long long b) {
    asm volatile("st.shared::cluster.v2.u64 [%0], {%1, %2};"
                 :: "r"(addr), "l"(a), "l"(b) : "memory");
}
__device__ __forceinline__ void dsmem_st_u32(unsigned addr, unsigned v) {
    asm volatile("st.shared::cluster.u32 [%0], %1;"
                 :: "r"(addr), "r"(v) : "memory");
}
// Arrive (release.cluster) on a pre-mapped remote mbarrier address.
// Orders all prior shared::cluster stores from this thread.
__device__ __forceinline__ void mbar_arrive_addr(unsigned remote_addr) {
    asm volatile(
        "mbarrier.arrive.release.cluster.shared::cluster.b64 _, [%0];"
        :: "r"(remote_addr) : "memory");
}
// Wait (acquire.cluster) on a LOCAL mbarrier for the given phase parity.
__device__ __forceinline__ void mbar_wait(unsigned addr, unsigned parity) {
    asm volatile(
        "{\n\t"
        ".reg .pred P;\n\t"
        "WL_%=:\n\t"
        "mbarrier.try_wait.parity.acquire.cluster.shared::cta.b64 P, [%0], %1, 0x989680;\n\t"
        "@!P bra WL_%=;\n\t"
        "}"
        :: "r"(addr), "r"(parity) : "memory");
}

// Mailbox slot: 16-byte aligned so {key, xy} moves as one v2.u64 / LDS.128.
struct alignas(16) Slot {
    unsigned long long key;
    unsigned long long xy;
};

// ---------------------------------------------------------------------------
// FPS: one cluster of 8 CTAs per batch; each thread owns 8 points (4 packed
// f32x2 pairs per coordinate) + 8 running min-distances in registers.
// Reductions are REDUX-based and 32-bit: (1) max over dist bits (dist >= 0,
// so u32-monotone), (2) min over the global index among threads holding the
// max — largest distance, ties to the SMALLEST index = jnp.argmax
// first-occurrence. Coordinates never ride the reduction: every thread dumps
// its candidate coords into per-tid smem slots (STS is issue-only and runs
// parallel to the REDUX chain; __syncthreads drains it); the block leader
// fetches the winner's coords with one LDS (winner tid = gk & 1023) and
// publishes {key,xy} + z to all 8 CTAs' mailboxes with ONE mapa per rank
// (z-store / arrive addresses derived by fixed smem deltas — remote window
// mapping is linear within a CTA's window). Cross-CTA handoff is an mbarrier
// producer/consumer (arrive.release.cluster / try_wait.acquire.cluster),
// double-buffered by iteration parity; no iteration re-loads the winner
// from global memory.
// ---------------------------------------------------------------------------
__global__ void __cluster_dims__(CLUSTER_X, 1, 1) __launch_bounds__(TPB, 1)
fps_kernel(const float* __restrict__ xyz)
{
    cg::cluster_group cluster = cg::this_cluster();
    const int rank = blockIdx.x;        // CTA rank within cluster
    const int b    = blockIdx.y;        // batch
    const int tid  = threadIdx.x;
    const int lane = tid & 31;
    const int wid  = tid >> 5;

    __shared__ unsigned long long cand_xy[TPB];   // per-thread candidate x,y
    __shared__ unsigned int       cand_z[TPB];    // per-thread candidate z
    __shared__ unsigned int       wdist[NWARP];
    __shared__ unsigned int       wgk[NWARP];
    __shared__ Slot               mslot[2][CLUSTER_X];
    __shared__ unsigned int       mzz[2][CLUSTER_X];
    __shared__ alignas(8) unsigned long long mbar[2];

    const unsigned mbar0 = smem_addr_u32(&mbar[0]);
    const unsigned mbar1 = smem_addr_u32(&mbar[1]);
    if (tid == 0) {
        mbar_init(mbar0, CLUSTER_X);   // 8 arrivals (one per CTA) per phase
        mbar_init(mbar1, CLUSTER_X);
    }
    __syncthreads();
    cluster.sync();  // one-time: all mbarriers initialized before any arrive

    const float* base = xyz + (size_t)b * KK * 3;

    // Register-resident points, packed in pairs: pair p holds points
    // (k0 + 2p*TPB, k0 + (2p+1)*TPB). Loads are coalesced across tid.
    unsigned long long px2[PAIRS], py2[PAIRS], pz2[PAIRS];
    float dist[PTS_PER_THREAD];
    const int k0 = rank * PTS_PER_CTA + tid;
#pragma unroll
    for (int p = 0; p < PAIRS; ++p) {
        const int ka = k0 + (2 * p) * TPB;
        const int kb = k0 + (2 * p + 1) * TPB;
        const float ax = base[(size_t)ka * 3 + 0];
        const float ay = base[(size_t)ka * 3 + 1];
        const float az = base[(size_t)ka * 3 + 2];
        const float bx = base[(size_t)kb * 3 + 0];
        const float by = base[(size_t)kb * 3 + 1];
        const float bz = base[(size_t)kb * 3 + 2];
        PACK_F32X2(px2[p], ax, bx);
        PACK_F32X2(py2[p], ay, by);
        PACK_F32X2(pz2[p], az, bz);
        dist[2 * p] = 1e10f;
        dist[2 * p + 1] = 1e10f;
    }

    if (rank == 0 && tid == 0) g_inds[b * NN + 0] = 0;  // first pick = index 0

    // Pivot for iteration 1: point 0 (uniform addr -> broadcast LDG; the
    // only winner-load from global memory in the whole kernel).
    float qx = __ldg(base + 0);
    float qy = __ldg(base + 1);
    float qz = __ldg(base + 2);

    int ph[2] = {0, 0};  // per-buffer phase parity (identical on all threads)

    for (int it = 1; it < NN; ++it) {
        // Negated pivot replicated into both f32x2 lanes (sub == add(-q))
        unsigned long long nqx2, nqy2, nqz2;
        {
            const float nx = -qx, ny = -qy, nz = -qz;
            PACK_F32X2(nqx2, nx, nx);
            PACK_F32X2(nqy2, ny, ny);
            PACK_F32X2(nqz2, nz, nz);
        }

        // Packed distance update: s = ((dx*dx + dy*dy) + dz*dz), no fma,
        // bit-identical per lane to the scalar/XLA computation.
#pragma unroll
        for (int p = 0; p < PAIRS; ++p) {
            unsigned long long dx2, dy2, dz2, sx2, sy2, sz2, s2;
            ADD_F32X2(dx2, px2[p], nqx2);
            ADD_F32X2(dy2, py2[p], nqy2);
            ADD_F32X2(dz2, pz2[p], nqz2);
            MUL_F32X2(sx2, dx2, dx2);
            MUL_F32X2(sy2, dy2, dy2);
            MUL_F32X2(sz2, dz2, dz2);
            ADD_F32X2(s2, sx2, sy2);
            ADD_F32X2(s2, s2, sz2);
            float sa, sb;
            UNPACK_F32X2(sa, sb, s2);
            dist[2 * p]     = fminf(dist[2 * p], sa);
            dist[2 * p + 1] = fminf(dist[2 * p + 1], sb);
        }

        // Per-thread argmax: parallel fmax tree, then equality bitmask +
        // ffs (lowest slot wins -> lowest global index on ties).
        const float m01 = fmaxf(dist[0], dist[1]);
        const float m23 = fmaxf(dist[2], dist[3]);
        const float m45 = fmaxf(dist[4], dist[5]);
        const float m67 = fmaxf(dist[6], dist[7]);
        const float bestd = fmaxf(fmaxf(m01, m23), fmaxf(m45, m67));
        unsigned msk = 0;
#pragma unroll
        for (int i = 0; i < PTS_PER_THREAD; ++i)
            msk |= (dist[i] == bestd) ? (1u << i) : 0u;
        const int besti = __ffs(msk) - 1;

        // Candidate coords -> per-tid smem slots. Select chain + STS run in
        // PARALLEL with the REDUX chain below (both branch from besti; STS
        // has no result latency and __syncthreads drains it).
        {
            unsigned long long bx2 = px2[0], by2 = py2[0], bz2 = pz2[0];
#pragma unroll
            for (int p = 1; p < PAIRS; ++p) {
                if ((besti >> 1) == p) { bx2 = px2[p]; by2 = py2[p]; bz2 = pz2[p]; }
            }
            float xlo, xhi, ylo, yhi, zlo, zhi;
            UNPACK_F32X2(xlo, xhi, bx2);
            UNPACK_F32X2(ylo, yhi, by2);
            UNPACK_F32X2(zlo, zhi, bz2);
            const int hsel = besti & 1;
            unsigned long long cxy;
            PACK_F32X2(cxy, hsel ? xhi : xlo, hsel ? yhi : ylo);
            cand_xy[tid] = cxy;
            cand_z[tid] = __float_as_uint(hsel ? zhi : zlo);
        }

        // Warp stage: REDUX max over dist bits (u32-monotone for dist>=0),
        // then REDUX min over gk among threads holding the max.
        const unsigned dbits = __float_as_uint(bestd);
        const unsigned gk = (unsigned)(k0 + besti * TPB);
        const unsigned wmaxd = __reduce_max_sync(0xFFFFFFFFu, dbits);
        const unsigned wmink =
            __reduce_min_sync(0xFFFFFFFFu,
                              (dbits == wmaxd) ? gk : 0xFFFFFFFFu);
        if (lane == 0) {
            wdist[wid] = wmaxd;
            wgk[wid] = wmink;
        }
        __syncthreads();  // publishes cand_* and w* to the whole CTA

        const int par = it & 1;
        const unsigned mb_local = par ? mbar1 : mbar0;
        if (wid == 0) {
            // Block stage: same REDUX pair over the 32 per-warp candidates
            const unsigned d2 = wdist[lane];
            const unsigned g2 = wgk[lane];
            const unsigned bmaxd = __reduce_max_sync(0xFFFFFFFFu, d2);
            const unsigned bmink =
                __reduce_min_sync(0xFFFFFFFFu,
                                  (d2 == bmaxd) ? g2 : 0xFFFFFFFFu);
            if (lane == 0) {
                // Winner's tid = gk & 1023 (rank*8192, besti*1024 are 0 mod
                // 1024): one LDS fetches its candidate coords.
                const unsigned bt = bmink & (TPB - 1);
                const unsigned long long x2 = cand_xy[bt];
                const unsigned z2v = cand_z[bt];
                const unsigned long long k2 =
                    ((unsigned long long)bmaxd << 32) |
                    (unsigned long long)(0xFFFFFFFFu - bmink);
                // ONE mapa per rank; z-store and arrive addresses derived by
                // fixed smem deltas (linear within the remote CTA window).
                const unsigned slot_local =
                    smem_addr_u32(&mslot[par][rank]);
                const int dz = (int)(smem_addr_u32(&mzz[par][rank]) -
                                     slot_local);
                const int dm = (int)(mb_local - slot_local);
#pragma unroll
                for (int r = 0; r < CLUSTER_X; ++r) {
                    const unsigned ra = mapa_rank(slot_local, (unsigned)r);
                    dsmem_st_v2u64(ra, k2, x2);
                    dsmem_st_u32(ra + dz, z2v);
                    mbar_arrive_addr(ra + dm);  // release: orders the stores
                }
            }
        }

        // All threads wait on the LOCAL mbarrier (8 arrivals -> phase flip)
        mbar_wait(mb_local, (unsigned)ph[par]);
        ph[par] ^= 1;

        // Key-only argmax over the 8 mailbox slots (broadcast LDS.128),
        // then a single coord fetch for the winning slot.
        unsigned long long bk = mslot[par][0].key;
        int br = 0;
#pragma unroll
        for (int r = 1; r < CLUSTER_X; ++r) {
            const unsigned long long ok = mslot[par][r].key;
            if (ok > bk) { bk = ok; br = r; }
        }
        UNPACK_F32X2(qx, qy, mslot[par][br].xy);
        qz = __uint_as_float(mzz[par][br]);

        if (rank == 0 && tid == 0) {
            g_inds[b * NN + it] =
                (int)(0xFFFFFFFFu - (unsigned)(bk & 0xFFFFFFFFull));
        }
    }

    cluster.sync();  // keep peer SMEM alive until all remote ops drained
}

// ---------------------------------------------------------------------------
// Gather new_xyz (B,n,3) + sample_inds-as-float (B,n)
// ---------------------------------------------------------------------------
__global__ void gather_xyz_inds_kernel(const float* __restrict__ xyz,
                                       float* __restrict__ out)
{
    const int t = blockIdx.x * blockDim.x + threadIdx.x;  // over B*N
    if (t >= BB * NN) return;
    const int b = t / NN;
    const int idx = g_inds[t];
    const float* src = xyz + ((size_t)b * KK + idx) * 3;
    float* o = out + (size_t)t * 3;
    o[0] = src[0];
    o[1] = src[1];
    o[2] = src[2];
    out[OFF_INDS + t] = (float)idx;
}

// ---------------------------------------------------------------------------
// Gather new_features (B,C,n): out[b,c,j] = feat[b,c,inds[b,j]]
// Writes coalesced over j; reads are an inherent 4B gather.
// ---------------------------------------------------------------------------
__global__ void gather_feat_kernel(const float* __restrict__ feat,
                                   float* __restrict__ out)
{
    const int j = blockIdx.x * blockDim.x + threadIdx.x;  // over N
    const int c = blockIdx.y;
    const int b = blockIdx.z;
    const int idx = g_inds[b * NN + j];
    out[OFF_FEAT + ((size_t)b * CC + c) * NN + j] =
        feat[((size_t)b * CC + c) * KK + idx];
}

// ---------------------------------------------------------------------------
extern "C" void kernel_launch(void* const* d_in, const int* in_sizes, int n_in,
                              void* d_out, int out_size)
{
    const float* xyz  = (const float*)d_in[0];  // (B, K, 3) float32
    const float* feat = (const float*)d_in[1];  // (B, C, K) float32
    float* out = (float*)d_out;

    // FPS: 8 clusters (one per batch) x 8 CTAs x 1024 threads
    fps_kernel<<<dim3(CLUSTER_X, BB, 1), TPB>>>(xyz);

    // Gathers (stream-ordered after FPS)
    gather_xyz_inds_kernel<<<(BB * NN + 255) / 256, 256>>>(xyz, out);
    gather_feat_kernel<<<dim3(NN / 256, CC, BB), 256>>>(feat, out);
}

// round 9
// speedup vs baseline: 1.5028x; 1.5028x over previous
#include <cuda_runtime.h>
#include <cooperative_groups.h>

namespace cg = cooperative_groups;

// Problem constants
#define BB 8
#define KK 65536
#define NN 1024
#define CC 128

// FPS kernel config
#define CLUSTER_X 8
#define TPB 1024
#define NWARP (TPB / 32)
#define PTS_PER_CTA (KK / CLUSTER_X)        // 8192
#define PTS_PER_THREAD (PTS_PER_CTA / TPB)  // 8
#define PAIRS (PTS_PER_THREAD / 2)          // 4

// Output layout (float32, concatenated in reference-return order):
//   [0,        BB*NN*3)                 new_xyz      (B, n, 3)
//   [OFF_FEAT, OFF_FEAT + BB*CC*NN)     new_features (B, C, n)
//   [OFF_INDS, OFF_INDS + BB*NN)        sample_inds  (B, n) as float
#define OFF_FEAT (BB * NN * 3)
#define OFF_INDS (OFF_FEAT + BB * CC * NN)

// Scratch for integer indices (device global: allocations are forbidden)
__device__ int g_inds[BB * NN];

// ---- packed f32x2 helpers (Blackwell FADD2/FMUL2; IEEE-exact per lane) ----
#define MUL_F32X2(out, a, b) \
    asm("mul.rn.f32x2 %0, %1, %2;" : "=l"(out) : "l"(a), "l"(b))
#define ADD_F32X2(out, a, b) \
    asm("add.rn.f32x2 %0, %1, %2;" : "=l"(out) : "l"(a), "l"(b))
#define PACK_F32X2(out, lo, hi) \
    asm("mov.b64 %0, {%1, %2};" : "=l"(out) : "f"(lo), "f"(hi))
#define UNPACK_F32X2(lo, hi, in) \
    asm("mov.b64 {%0, %1}, %2;" : "=f"(lo), "=f"(hi) : "l"(in))

// ---- mbarrier / DSMEM helpers ----
__device__ __forceinline__ unsigned smem_addr_u32(const void* p) {
    return (unsigned)__cvta_generic_to_shared(p);
}
__device__ __forceinline__ void mbar_init(unsigned addr, unsigned count) {
    asm volatile("mbarrier.init.shared.b64 [%0], %1;" :: "r"(addr), "r"(count)
                 : "memory");
}
// Map a local shared address into cluster CTA `rank`'s window.
__device__ __forceinline__ unsigned mapa_rank(unsigned local_addr,
                                              unsigned rank) {
    unsigned ra;
    asm volatile("mapa.shared::cluster.u32 %0, %1, %2;"
                 : "=r"(ra) : "r"(local_addr), "r"(rank));
    return ra;
}
__device__ __forceinline__ void dsmem_st_v2u64(unsigned addr,
                                               unsigned long long a,
                                               unsigned long long b) {
    asm volatile("st.shared::cluster.v2.u64 [%0], {%1, %2};"
                 :: "r"(addr), "l"(a), "l"(b) : "memory");
}
__device__ __forceinline__ void dsmem_st_u32(unsigned addr, unsigned v) {
    asm volatile("st.shared::cluster.u32 [%0], %1;"
                 :: "r"(addr), "r"(v) : "memory");
}
// Arrive (release.cluster) on a pre-mapped remote mbarrier address.
// Orders all prior shared::cluster stores from THIS thread.
__device__ __forceinline__ void mbar_arrive_addr(unsigned remote_addr) {
    asm volatile(
        "mbarrier.arrive.release.cluster.shared::cluster.b64 _, [%0];"
        :: "r"(remote_addr) : "memory");
}
// Wait (acquire.cluster) on a LOCAL mbarrier for the given phase parity.
// TIGHT POLL: suspendTimeHint = 64 ns. The wait ALWAYS fails on first probe
// in this kernel (leader hasn't published yet), so a large hint (the usual
// 0x989680 = 10 ms) sends warps into deep HW sleep with a coarse wakeup —
// the prime suspect for the measured 74%-idle iteration time.
__device__ __forceinline__ void mbar_wait(unsigned addr, unsigned parity) {
    asm volatile(
        "{\n\t"
        ".reg .pred P;\n\t"
        "WL_%=:\n\t"
        "mbarrier.try_wait.parity.acquire.cluster.shared::cta.b64 P, [%0], %1, 64;\n\t"
        "@!P bra WL_%=;\n\t"
        "}"
        :: "r"(addr), "r"(parity) : "memory");
}

// Mailbox slot: 16-byte aligned so {key, xy} moves as one v2.u64 / LDS.128.
struct alignas(16) Slot {
    unsigned long long key;
    unsigned long long xy;
};

// ---------------------------------------------------------------------------
// FPS: one cluster of 8 CTAs per batch; each thread owns 8 points (4 packed
// f32x2 pairs per coordinate) + 8 running min-distances in registers.
// Reductions are REDUX-based and 32-bit: (1) max over dist bits (dist >= 0,
// so u32-monotone), (2) min over the global index among threads holding the
// max — largest distance, ties to the SMALLEST index = jnp.argmax
// first-occurrence. Coordinates never ride the reduction: every thread dumps
// its candidate coords into per-tid smem slots; after the block REDUX, ALL
// 32 lanes of warp 0 hold the winner, and lanes 0..7 publish IN PARALLEL —
// lane r maps the slot into rank r and issues {key,xy} + z + arrive. Each
// CTA's mbarrier receives exactly 8 release-ordered arrives per phase (one
// from each CTA); per-lane stores are ordered by that lane's own arrive.
// Double-buffered by iteration parity; no iteration re-loads the winner
// from global memory.
// ---------------------------------------------------------------------------
__global__ void __cluster_dims__(CLUSTER_X, 1, 1) __launch_bounds__(TPB, 1)
fps_kernel(const float* __restrict__ xyz)
{
    cg::cluster_group cluster = cg::this_cluster();
    const int rank = blockIdx.x;        // CTA rank within cluster
    const int b    = blockIdx.y;        // batch
    const int tid  = threadIdx.x;
    const int lane = tid & 31;
    const int wid  = tid >> 5;

    __shared__ unsigned long long cand_xy[TPB];   // per-thread candidate x,y
    __shared__ unsigned int       cand_z[TPB];    // per-thread candidate z
    __shared__ unsigned int       wdist[NWARP];
    __shared__ unsigned int       wgk[NWARP];
    __shared__ Slot               mslot[2][CLUSTER_X];
    __shared__ unsigned int       mzz[2][CLUSTER_X];
    __shared__ alignas(8) unsigned long long mbar[2];

    const unsigned mbar0 = smem_addr_u32(&mbar[0]);
    const unsigned mbar1 = smem_addr_u32(&mbar[1]);
    if (tid == 0) {
        mbar_init(mbar0, CLUSTER_X);   // 8 arrivals (one per CTA) per phase
        mbar_init(mbar1, CLUSTER_X);
    }
    __syncthreads();
    cluster.sync();  // one-time: all mbarriers initialized before any arrive

    const float* base = xyz + (size_t)b * KK * 3;

    // Register-resident points, packed in pairs: pair p holds points
    // (k0 + 2p*TPB, k0 + (2p+1)*TPB). Loads are coalesced across tid.
    unsigned long long px2[PAIRS], py2[PAIRS], pz2[PAIRS];
    float dist[PTS_PER_THREAD];
    const int k0 = rank * PTS_PER_CTA + tid;
#pragma unroll
    for (int p = 0; p < PAIRS; ++p) {
        const int ka = k0 + (2 * p) * TPB;
        const int kb = k0 + (2 * p + 1) * TPB;
        const float ax = base[(size_t)ka * 3 + 0];
        const float ay = base[(size_t)ka * 3 + 1];
        const float az = base[(size_t)ka * 3 + 2];
        const float bx = base[(size_t)kb * 3 + 0];
        const float by = base[(size_t)kb * 3 + 1];
        const float bz = base[(size_t)kb * 3 + 2];
        PACK_F32X2(px2[p], ax, bx);
        PACK_F32X2(py2[p], ay, by);
        PACK_F32X2(pz2[p], az, bz);
        dist[2 * p] = 1e10f;
        dist[2 * p + 1] = 1e10f;
    }

    if (rank == 0 && tid == 0) g_inds[b * NN + 0] = 0;  // first pick = index 0

    // Pivot for iteration 1: point 0 (uniform addr -> broadcast LDG; the
    // only winner-load from global memory in the whole kernel).
    float qx = __ldg(base + 0);
    float qy = __ldg(base + 1);
    float qz = __ldg(base + 2);

    int ph[2] = {0, 0};  // per-buffer phase parity (identical on all threads)

    for (int it = 1; it < NN; ++it) {
        // Negated pivot replicated into both f32x2 lanes (sub == add(-q))
        unsigned long long nqx2, nqy2, nqz2;
        {
            const float nx = -qx, ny = -qy, nz = -qz;
            PACK_F32X2(nqx2, nx, nx);
            PACK_F32X2(nqy2, ny, ny);
            PACK_F32X2(nqz2, nz, nz);
        }

        // Packed distance update: s = ((dx*dx + dy*dy) + dz*dz), no fma,
        // bit-identical per lane to the scalar/XLA computation.
#pragma unroll
        for (int p = 0; p < PAIRS; ++p) {
            unsigned long long dx2, dy2, dz2, sx2, sy2, sz2, s2;
            ADD_F32X2(dx2, px2[p], nqx2);
            ADD_F32X2(dy2, py2[p], nqy2);
            ADD_F32X2(dz2, pz2[p], nqz2);
            MUL_F32X2(sx2, dx2, dx2);
            MUL_F32X2(sy2, dy2, dy2);
            MUL_F32X2(sz2, dz2, dz2);
            ADD_F32X2(s2, sx2, sy2);
            ADD_F32X2(s2, s2, sz2);
            float sa, sb;
            UNPACK_F32X2(sa, sb, s2);
            dist[2 * p]     = fminf(dist[2 * p], sa);
            dist[2 * p + 1] = fminf(dist[2 * p + 1], sb);
        }

        // Per-thread argmax: parallel fmax tree, then equality bitmask +
        // ffs (lowest slot wins -> lowest global index on ties).
        const float m01 = fmaxf(dist[0], dist[1]);
        const float m23 = fmaxf(dist[2], dist[3]);
        const float m45 = fmaxf(dist[4], dist[5]);
        const float m67 = fmaxf(dist[6], dist[7]);
        const float bestd = fmaxf(fmaxf(m01, m23), fmaxf(m45, m67));
        unsigned msk = 0;
#pragma unroll
        for (int i = 0; i < PTS_PER_THREAD; ++i)
            msk |= (dist[i] == bestd) ? (1u << i) : 0u;
        const int besti = __ffs(msk) - 1;

        // Candidate coords -> per-tid smem slots. Select chain + STS run in
        // PARALLEL with the REDUX chain below (both branch from besti; STS
        // has no result latency and __syncthreads drains it).
        {
            unsigned long long bx2 = px2[0], by2 = py2[0], bz2 = pz2[0];
#pragma unroll
            for (int p = 1; p < PAIRS; ++p) {
                if ((besti >> 1) == p) { bx2 = px2[p]; by2 = py2[p]; bz2 = pz2[p]; }
            }
            float xlo, xhi, ylo, yhi, zlo, zhi;
            UNPACK_F32X2(xlo, xhi, bx2);
            UNPACK_F32X2(ylo, yhi, by2);
            UNPACK_F32X2(zlo, zhi, bz2);
            const int hsel = besti & 1;
            unsigned long long cxy;
            PACK_F32X2(cxy, hsel ? xhi : xlo, hsel ? yhi : ylo);
            cand_xy[tid] = cxy;
            cand_z[tid] = __float_as_uint(hsel ? zhi : zlo);
        }

        // Warp stage: REDUX max over dist bits (u32-monotone for dist>=0),
        // then REDUX min over gk among threads holding the max.
        const unsigned dbits = __float_as_uint(bestd);
        const unsigned gk = (unsigned)(k0 + besti * TPB);
        const unsigned wmaxd = __reduce_max_sync(0xFFFFFFFFu, dbits);
        const unsigned wmink =
            __reduce_min_sync(0xFFFFFFFFu,
                              (dbits == wmaxd) ? gk : 0xFFFFFFFFu);
        if (lane == 0) {
            wdist[wid] = wmaxd;
            wgk[wid] = wmink;
        }
        __syncthreads();  // publishes cand_* and w* to the whole CTA

        const int par = it & 1;
        const unsigned mb_local = par ? mbar1 : mbar0;
        if (wid == 0) {
            // Block stage: same REDUX pair over the 32 per-warp candidates.
            // ALL lanes end up holding the block winner.
            const unsigned d2 = wdist[lane];
            const unsigned g2 = wgk[lane];
            const unsigned bmaxd = __reduce_max_sync(0xFFFFFFFFu, d2);
            const unsigned bmink =
                __reduce_min_sync(0xFFFFFFFFu,
                                  (d2 == bmaxd) ? g2 : 0xFFFFFFFFu);
            if (lane < CLUSTER_X) {
                // PARALLEL publish: lane r handles rank r. Winner tid =
                // gk & 1023 (rank*8192, besti*1024 are 0 mod 1024); the
                // coord fetch is a broadcast LDS (uniform address).
                const unsigned bt = bmink & (TPB - 1);
                const unsigned long long x2 = cand_xy[bt];
                const unsigned z2v = cand_z[bt];
                const unsigned long long k2 =
                    ((unsigned long long)bmaxd << 32) |
                    (unsigned long long)(0xFFFFFFFFu - bmink);
                const unsigned slot_local =
                    smem_addr_u32(&mslot[par][rank]);
                const int dz = (int)(smem_addr_u32(&mzz[par][rank]) -
                                     slot_local);
                const int dm = (int)(mb_local - slot_local);
                const unsigned ra = mapa_rank(slot_local, (unsigned)lane);
                dsmem_st_v2u64(ra, k2, x2);
                dsmem_st_u32(ra + dz, z2v);
                mbar_arrive_addr(ra + dm);  // release: orders THIS lane's stores
            }
        }

        // All threads wait on the LOCAL mbarrier (8 arrivals -> phase flip)
        mbar_wait(mb_local, (unsigned)ph[par]);
        ph[par] ^= 1;

        // Key-only argmax over the 8 mailbox slots (broadcast LDS.128),
        // then a single coord fetch for the winning slot.
        unsigned long long bk = mslot[par][0].key;
        int br = 0;
#pragma unroll
        for (int r = 1; r < CLUSTER_X; ++r) {
            const unsigned long long ok = mslot[par][r].key;
            if (ok > bk) { bk = ok; br = r; }
        }
        UNPACK_F32X2(qx, qy, mslot[par][br].xy);
        qz = __uint_as_float(mzz[par][br]);

        if (rank == 0 && tid == 0) {
            g_inds[b * NN + it] =
                (int)(0xFFFFFFFFu - (unsigned)(bk & 0xFFFFFFFFull));
        }
    }

    cluster.sync();  // keep peer SMEM alive until all remote ops drained
}

// ---------------------------------------------------------------------------
// Gather new_xyz (B,n,3) + sample_inds-as-float (B,n)
// ---------------------------------------------------------------------------
__global__ void gather_xyz_inds_kernel(const float* __restrict__ xyz,
                                       float* __restrict__ out)
{
    const int t = blockIdx.x * blockDim.x + threadIdx.x;  // over B*N
    if (t >= BB * NN) return;
    const int b = t / NN;
    const int idx = g_inds[t];
    const float* src = xyz + ((size_t)b * KK + idx) * 3;
    float* o = out + (size_t)t * 3;
    o[0] = src[0];
    o[1] = src[1];
    o[2] = src[2];
    out[OFF_INDS + t] = (float)idx;
}

// ---------------------------------------------------------------------------
// Gather new_features (B,C,n): out[b,c,j] = feat[b,c,inds[b,j]]
// Writes coalesced over j; reads are an inherent 4B gather.
// ---------------------------------------------------------------------------
__global__ void gather_feat_kernel(const float* __restrict__ feat,
                                   float* __restrict__ out)
{
    const int j = blockIdx.x * blockDim.x + threadIdx.x;  // over N
    const int c = blockIdx.y;
    const int b = blockIdx.z;
    const int idx = g_inds[b * NN + j];
    out[OFF_FEAT + ((size_t)b * CC + c) * NN + j] =
        feat[((size_t)b * CC + c) * KK + idx];
}

// ---------------------------------------------------------------------------
extern "C" void kernel_launch(void* const* d_in, const int* in_sizes, int n_in,
                              void* d_out, int out_size)
{
    const float* xyz  = (const float*)d_in[0];  // (B, K, 3) float32
    const float* feat = (const float*)d_in[1];  // (B, C, K) float32
    float* out = (float*)d_out;

    // FPS: 8 clusters (one per batch) x 8 CTAs x 1024 threads
    fps_kernel<<<dim3(CLUSTER_X, BB, 1), TPB>>>(xyz);

    // Gathers (stream-ordered after FPS)
    gather_xyz_inds_kernel<<<(BB * NN + 255) / 256, 256>>>(xyz, out);
    gather_feat_kernel<<<dim3(NN / 256, CC, BB), 256>>>(feat, out);
}